// round 1
// baseline (speedup 1.0000x reference)
#include <cuda_runtime.h>
#include <cstddef>

// ---------------------------------------------------------------------------
// Problem constants (shapes are fixed by the dataset)
// ---------------------------------------------------------------------------
// prev_feat / next_feat : [8, 32, 48, 48, 48] f32
// phi                   : [8, 1, 96, 96, 96]  f32
// stream                : [8, 3, 96, 96, 96]  f32
// outputs (concatenated in d_out, f32):
//   corr       [8, 27, 48, 48, 48]   = 23,887,872
//   vel        [8, 3, 94, 94, 94]    = 19,934,016
//   vel_phi    [8, 3, 94, 94, 94]
//   vel_stream [8, 3, 94, 94, 94]

namespace {
constexpr int C  = 32;
constexpr int D  = 48;                // X = Y = Z for features
constexpr int SX = D * D;             // 2304
constexpr int SY = D;                 // 48
constexpr long SC  = (long)D * D * D; // 110592  (channel stride)
constexpr long SBF = (long)C * SC;    // feat batch stride

constexpr int H = 96;                 // phi/stream spatial
constexpr int O = 94;                 // output spatial
constexpr long HS = (long)H * H * H;  // 884736
constexpr long OS = (long)O * O * O;  // 830584

constexpr long CORR_ELEMS = 8L * 27 * SC;     // 23,887,872
constexpr long VEL_ELEMS  = 8L * 3 * OS;      // 19,934,016
}

// ---------------------------------------------------------------------------
// Kernel 1: correlation. Thread = (b, x, y, z4) handling 4 contiguous z.
// Only 9 distinct correlations; write them 3x with z-edge masks.
// ---------------------------------------------------------------------------
__global__ __launch_bounds__(192)
void corr_kernel(const float* __restrict__ prev,
                 const float* __restrict__ nxt,
                 float* __restrict__ out) {
    const int z4 = threadIdx.x;                       // 0..11
    const int y  = blockIdx.y * blockDim.y + threadIdx.y;
    const int x  = blockIdx.x;
    const int b  = blockIdx.z;
    const int z  = z4 * 4;

    const size_t base = (size_t)b * SBF + (size_t)x * SX + (size_t)y * SY + z;

    bool vx[3], vy[3];
    vx[0] = (x > 0);     vx[1] = true; vx[2] = (x < D - 1);
    vy[0] = (y > 0);     vy[1] = true; vy[2] = (y < D - 1);

    float4 acc[9];
    #pragma unroll
    for (int d = 0; d < 9; d++) acc[d] = make_float4(0.f, 0.f, 0.f, 0.f);

    #pragma unroll 4
    for (int c = 0; c < C; c++) {
        const size_t cb = base + (size_t)c * SC;
        const float4 p = *reinterpret_cast<const float4*>(prev + cb);
        const float* nb = nxt + cb;
        #pragma unroll
        for (int ix = 0; ix < 3; ix++) {
            #pragma unroll
            for (int iy = 0; iy < 3; iy++) {
                float4 n = make_float4(0.f, 0.f, 0.f, 0.f);
                if (vx[ix] && vy[iy])
                    n = *reinterpret_cast<const float4*>(
                        nb + (ix - 1) * SX + (iy - 1) * SY);
                const int d = ix * 3 + iy;
                acc[d].x += p.x * n.x;
                acc[d].y += p.y * n.y;
                acc[d].z += p.z * n.z;
                acc[d].w += p.w * n.w;
            }
        }
    }

    const float inv = 1.0f / 32.0f;
    const size_t ob = (size_t)b * 27 * SC + (size_t)x * SX + (size_t)y * SY + z;

    #pragma unroll
    for (int d = 0; d < 9; d++) {
        float4 v = acc[d];
        v.x *= inv; v.y *= inv; v.z *= inv; v.w *= inv;

        // k = 0 channels 9..17 : unmasked
        *reinterpret_cast<float4*>(out + ob + (size_t)(9 + d) * SC) = v;

        // k = -1 channels 0..8 : zero at z == 47
        float4 vm = v;
        if (z4 == 11) vm.w = 0.f;
        *reinterpret_cast<float4*>(out + ob + (size_t)d * SC) = vm;

        // k = +1 channels 18..26 : zero at z == 0
        float4 vp = v;
        if (z4 == 0) vp.x = 0.f;
        *reinterpret_cast<float4*>(out + ob + (size_t)(18 + d) * SC) = vp;
    }
}

// ---------------------------------------------------------------------------
// Kernel 2: velocities. All _fdiff edge cases are unreachable for the crop
// window, so everything is plain differences. Thread = (b,i,j,k).
// ---------------------------------------------------------------------------
__device__ __forceinline__ size_t idxH(int x, int y, int z) {
    return ((size_t)x * H + y) * H + z;
}

__global__ __launch_bounds__(96)
void vel_kernel(const float* __restrict__ phi,
                const float* __restrict__ stream,
                float* __restrict__ vel,
                float* __restrict__ vphi,
                float* __restrict__ vstr) {
    const int k = threadIdx.x;
    if (k >= O) return;
    const int j = blockIdx.x;
    const int i = blockIdx.y;
    const int b = blockIdx.z;

    const float* P  = phi + (size_t)b * HS;
    const float* s0 = stream + (size_t)b * 3 * HS;
    const float* s1 = s0 + HS;
    const float* s2 = s0 + 2 * HS;

    // phi velocity (central differences)
    const float pu = 0.5f * (P[idxH(i + 1, j + 1, k + 2)] - P[idxH(i + 1, j + 1, k)]);
    const float pv = 0.5f * (P[idxH(i + 1, j + 2, k + 1)] - P[idxH(i + 1, j, k + 1)]);
    const float pw = 0.5f * (P[idxH(i + 2, j + 1, k + 1)] - P[idxH(i, j + 1, k + 1)]);

    // stream (curl-like) velocity
    float su = 0.f, sv = 0.f, sw = 0.f;
    #pragma unroll
    for (int t = 0; t < 2; t++) {
        const int z = k + t;
        su += s1[idxH(i + 2, j + 1, z)] - s1[idxH(i + 1, j + 1, z)]
            - s0[idxH(i + 1, j + 2, z)] + s0[idxH(i + 1, j + 1, z)];
    }
    #pragma unroll
    for (int t = 0; t < 2; t++) {
        const int y = j + t;
        sv += s0[idxH(i + 1, y, k + 2)] - s0[idxH(i + 1, y, k + 1)]
            - s2[idxH(i + 2, y, k + 1)] + s2[idxH(i + 1, y, k + 1)];
    }
    #pragma unroll
    for (int t = 0; t < 2; t++) {
        const int x = i + t;
        sw += s2[idxH(x, j + 2, k + 1)] - s2[idxH(x, j + 1, k + 1)]
            - s1[idxH(x, j + 1, k + 2)] + s1[idxH(x, j + 1, k + 1)];
    }
    su *= 0.5f; sv *= 0.5f; sw *= 0.5f;

    const size_t o0 = (((size_t)(b * 3 + 0) * O + i) * O + j) * O + k;

    vphi[o0]          = pu;
    vphi[o0 + OS]     = pv;
    vphi[o0 + 2 * OS] = pw;

    vstr[o0]          = su;
    vstr[o0 + OS]     = sv;
    vstr[o0 + 2 * OS] = sw;

    vel[o0]           = pu + su;
    vel[o0 + OS]      = pv + sv;
    vel[o0 + 2 * OS]  = pw + sw;
}

// ---------------------------------------------------------------------------
// Launch
// ---------------------------------------------------------------------------
extern "C" void kernel_launch(void* const* d_in, const int* in_sizes, int n_in,
                              void* d_out, int out_size) {
    const float* prev   = (const float*)d_in[0];
    const float* nxt    = (const float*)d_in[1];
    const float* phi    = (const float*)d_in[2];
    const float* stream = (const float*)d_in[3];

    float* out  = (float*)d_out;
    float* corr = out;
    float* vel  = out + CORR_ELEMS;
    float* vphi = vel + VEL_ELEMS;
    float* vstr = vphi + VEL_ELEMS;

    {
        dim3 blk(12, 16, 1);          // 12 float4 z-groups x 16 y rows
        dim3 grd(D, D / 16, 8);       // (x, y-tiles, b)
        corr_kernel<<<grd, blk>>>(prev, nxt, corr);
    }
    {
        dim3 blk(96, 1, 1);           // k line (94 active)
        dim3 grd(O, O, 8);            // (j, i, b)
        vel_kernel<<<grd, blk>>>(phi, stream, vel, vphi, vstr);
    }
}